// round 2
// baseline (speedup 1.0000x reference)
#include <cuda_runtime.h>
#include <cuda_bf16.h>

#define NRELS 20

// ---------------------------------------------------------------------------
// Per-edge math, shared by both kernels.
// ---------------------------------------------------------------------------
__device__ __forceinline__ void edge_compute(
    float p0, float p1, float p2,
    float c0, float c1, float c2,
    const float* __restrict__ mu, const float* __restrict__ sg,
    const float* ep,   // 9 floats
    float b,
    float& cm, float& ocp0, float& ocp1, float& ocp2,
    float& am, float& oal0, float& oal1, float& oal2)
{
    // M = mu + sigma*eps ; logits = M @ child
    float l0 = fmaf(fmaf(sg[0], ep[0], mu[0]), c0,
               fmaf(fmaf(sg[1], ep[1], mu[1]), c1,
                    fmaf(sg[2], ep[2], mu[2]) * c2));
    float l1 = fmaf(fmaf(sg[3], ep[3], mu[3]), c0,
               fmaf(fmaf(sg[4], ep[4], mu[4]), c1,
                    fmaf(sg[5], ep[5], mu[5]) * c2));
    float l2 = fmaf(fmaf(sg[6], ep[6], mu[6]), c0,
               fmaf(fmaf(sg[7], ep[7], mu[7]), c1,
                    fmaf(sg[8], ep[8], mu[8]) * c2));

    // softmax (max-subtracted)
    float m  = fmaxf(l0, fmaxf(l1, l2));
    float e0 = __expf(l0 - m);
    float e1 = __expf(l1 - m);
    float e2 = __expf(l2 - m);
    float inv_es = __frcp_rn(e0 + e1 + e2);
    float cp0 = e0 * inv_es;
    float cp1 = e1 * inv_es;
    float cp2 = e2 * inv_es;

    // masks (exact-zero semantics)
    float child_sum = c0 + c1 + c2;
    float prnt_sum  = p0 + p1 + p2;
    bool child_mask = (child_sum != 0.0f);
    bool copy_mask  = child_mask && (prnt_sum == 0.0f);
    bool alpha_mask = child_mask && (prnt_sum != 0.0f);

    // scale: z clamp/normalize -> entropy; cosine
    float z0 = fmaxf(0.01f, p0 + cp0);
    float z1 = fmaxf(0.01f, p1 + cp1);
    float z2 = fmaxf(0.01f, p2 + cp2);
    float inv_zs = __frcp_rn(z0 + z1 + z2);
    z0 *= inv_zs; z1 *= inv_zs; z2 *= inv_zs;
    float entropy = -(z0 * __logf(z0) + z1 * __logf(z1) + z2 * __logf(z2));

    float dot  = p0 * cp0 + p1 * cp1 + p2 * cp2;
    float sqp  = p0 * p0 + p1 * p1 + p2 * p2;
    float sqc  = cp0 * cp0 + cp1 * cp1 + cp2 * cp2;
    float np   = (sqp == 0.0f) ? 0.0f : __fsqrt_rn(sqp);
    float nc   = (sqc == 0.0f) ? 0.0f : __fsqrt_rn(sqc);
    float norm = np * nc;
    norm = (norm == 0.0f) ? 1.0f : norm;
    float cosv = fmaxf(0.01f, dot * __frcp_rn(norm));
    float s = 42.0f * cosv * __frcp_rn(entropy);

    float ob = 1.0f - b;
    float a0 = fmaf(ob, p0, b * cp0) * s;
    float a1 = fmaf(ob, p1, b * cp1) * s;
    float a2 = fmaf(ob, p2, b * cp2) * s;

    cm   = copy_mask ? 1.0f : 0.0f;
    ocp0 = copy_mask ? cp0 : 0.0f;
    ocp1 = copy_mask ? cp1 : 0.0f;
    ocp2 = copy_mask ? cp2 : 0.0f;
    am   = alpha_mask ? 1.0f : 0.0f;
    oal0 = alpha_mask ? a0 : 0.0f;
    oal1 = alpha_mask ? a1 : 0.0f;
    oal2 = alpha_mask ? a2 : 0.0f;
}

// ---------------------------------------------------------------------------
// Vectorized kernel: 4 edges per thread, all traffic via float4/int4.
// Requires n % 4 == 0 (the bench shape is 4,000,000).
// ---------------------------------------------------------------------------
__global__ __launch_bounds__(256)
void alpha_model_vec4(const float4* __restrict__ prnt4,
                      const float4* __restrict__ child4,
                      const float*  __restrict__ rel_mu,
                      const float*  __restrict__ rel_sigma,
                      const float4* __restrict__ eps4,
                      const float4* __restrict__ beta4,
                      const int4*   __restrict__ rels4,
                      float4* __restrict__ out4,
                      int nq)   // nq = n/4
{
    __shared__ float s_mu[NRELS * 9];
    __shared__ float s_sig[NRELS * 9];
    for (int t = threadIdx.x; t < NRELS * 9; t += blockDim.x) {
        s_mu[t]  = rel_mu[t];
        s_sig[t] = rel_sigma[t];
    }
    __syncthreads();

    int t = blockIdx.x * blockDim.x + threadIdx.x;
    if (t >= nq) return;

    // ---- issue ALL loads up front (17 independent 16B LDGs -> deep MLP) ----
    int4   rv = rels4[t];
    float4 bv = beta4[t];

    float4 pA = prnt4[3 * (size_t)t + 0];
    float4 pB = prnt4[3 * (size_t)t + 1];
    float4 pC = prnt4[3 * (size_t)t + 2];
    float4 cA = child4[3 * (size_t)t + 0];
    float4 cB = child4[3 * (size_t)t + 1];
    float4 cC = child4[3 * (size_t)t + 2];

    float4 e4[9];
    const float4* epv = eps4 + 9 * (size_t)t;
    #pragma unroll
    for (int k = 0; k < 9; k++) e4[k] = epv[k];

    // ---- unpack into constant-indexed register arrays ----
    float pf[12] = { pA.x, pA.y, pA.z, pA.w, pB.x, pB.y, pB.z, pB.w,
                     pC.x, pC.y, pC.z, pC.w };
    float cf[12] = { cA.x, cA.y, cA.z, cA.w, cB.x, cB.y, cB.z, cB.w,
                     cC.x, cC.y, cC.z, cC.w };
    float ef[36];
    #pragma unroll
    for (int k = 0; k < 9; k++) {
        ef[4 * k + 0] = e4[k].x;
        ef[4 * k + 1] = e4[k].y;
        ef[4 * k + 2] = e4[k].z;
        ef[4 * k + 3] = e4[k].w;
    }
    float bf[4] = { bv.x, bv.y, bv.z, bv.w };
    int   rf[4] = { rv.x, rv.y, rv.z, rv.w };

    float cm[4], am[4], cpv[12], alv[12];

    #pragma unroll
    for (int j = 0; j < 4; j++) {
        const float* mu = &s_mu[9 * rf[j]];
        const float* sg = &s_sig[9 * rf[j]];
        edge_compute(pf[3 * j], pf[3 * j + 1], pf[3 * j + 2],
                     cf[3 * j], cf[3 * j + 1], cf[3 * j + 2],
                     mu, sg, &ef[9 * j], bf[j],
                     cm[j], cpv[3 * j], cpv[3 * j + 1], cpv[3 * j + 2],
                     am[j], alv[3 * j], alv[3 * j + 1], alv[3 * j + 2]);
    }

    // ---- vectorized stores ----
    size_t NQ = nq;   // quarter-N; out sections in float4 units: mask NQ, vec 3NQ
    out4[t] = make_float4(cm[0], cm[1], cm[2], cm[3]);

    float4* ocp = out4 + NQ + 3 * (size_t)t;
    ocp[0] = make_float4(cpv[0], cpv[1], cpv[2],  cpv[3]);
    ocp[1] = make_float4(cpv[4], cpv[5], cpv[6],  cpv[7]);
    ocp[2] = make_float4(cpv[8], cpv[9], cpv[10], cpv[11]);

    out4[4 * NQ + t] = make_float4(am[0], am[1], am[2], am[3]);

    float4* oal = out4 + 5 * NQ + 3 * (size_t)t;
    oal[0] = make_float4(alv[0], alv[1], alv[2],  alv[3]);
    oal[1] = make_float4(alv[4], alv[5], alv[6],  alv[7]);
    oal[2] = make_float4(alv[8], alv[9], alv[10], alv[11]);
}

// ---------------------------------------------------------------------------
// Scalar fallback (any n).
// ---------------------------------------------------------------------------
__global__ __launch_bounds__(256)
void alpha_model_scalar(const float* __restrict__ prnt,
                        const float* __restrict__ child,
                        const float* __restrict__ rel_mu,
                        const float* __restrict__ rel_sigma,
                        const float* __restrict__ eps,
                        const float* __restrict__ beta,
                        const int*   __restrict__ rels,
                        float* __restrict__ out,
                        int n)
{
    __shared__ float s_mu[NRELS * 9];
    __shared__ float s_sig[NRELS * 9];
    for (int t = threadIdx.x; t < NRELS * 9; t += blockDim.x) {
        s_mu[t]  = rel_mu[t];
        s_sig[t] = rel_sigma[t];
    }
    __syncthreads();

    int i = blockIdx.x * blockDim.x + threadIdx.x;
    if (i >= n) return;

    int r = rels[i];
    float b = beta[i];
    float p0 = prnt[3 * i + 0], p1 = prnt[3 * i + 1], p2 = prnt[3 * i + 2];
    float c0 = child[3 * i + 0], c1 = child[3 * i + 1], c2 = child[3 * i + 2];
    float ep[9];
    #pragma unroll
    for (int k = 0; k < 9; k++) ep[k] = eps[9 * (size_t)i + k];

    float cm, ocp0, ocp1, ocp2, am, oal0, oal1, oal2;
    edge_compute(p0, p1, p2, c0, c1, c2, &s_mu[9 * r], &s_sig[9 * r], ep, b,
                 cm, ocp0, ocp1, ocp2, am, oal0, oal1, oal2);

    size_t N = n;
    out[i] = cm;
    out[N + 3 * (size_t)i + 0] = ocp0;
    out[N + 3 * (size_t)i + 1] = ocp1;
    out[N + 3 * (size_t)i + 2] = ocp2;
    out[4 * N + i] = am;
    out[5 * N + 3 * (size_t)i + 0] = oal0;
    out[5 * N + 3 * (size_t)i + 1] = oal1;
    out[5 * N + 3 * (size_t)i + 2] = oal2;
}

extern "C" void kernel_launch(void* const* d_in, const int* in_sizes, int n_in,
                              void* d_out, int out_size) {
    const float* prnt   = (const float*)d_in[0];
    const float* child  = (const float*)d_in[1];
    const float* rel_mu = (const float*)d_in[2];
    const float* rel_sg = (const float*)d_in[3];
    const float* eps    = (const float*)d_in[4];
    const float* beta   = (const float*)d_in[5];
    const int*   rels   = (const int*)d_in[6];
    float* out = (float*)d_out;

    int n = in_sizes[5];  // beta element count == N
    if ((n & 3) == 0) {
        int nq = n >> 2;
        int threads = 256;
        int blocks = (nq + threads - 1) / threads;
        alpha_model_vec4<<<blocks, threads>>>(
            (const float4*)prnt, (const float4*)child, rel_mu, rel_sg,
            (const float4*)eps, (const float4*)beta, (const int4*)rels,
            (float4*)out, nq);
    } else {
        int threads = 256;
        int blocks = (n + threads - 1) / threads;
        alpha_model_scalar<<<blocks, threads>>>(prnt, child, rel_mu, rel_sg,
                                                eps, beta, rels, out, n);
    }
}

// round 5
// speedup vs baseline: 1.0816x; 1.0816x over previous
#include <cuda_runtime.h>
#include <cuda_bf16.h>

#define NRELS 20
#define EPB 256   // edges per block == threads per block

// ---------------------------------------------------------------------------
// Per-edge math.
// ---------------------------------------------------------------------------
__device__ __forceinline__ void edge_compute(
    float p0, float p1, float p2,
    float c0, float c1, float c2,
    const float* __restrict__ mu, const float* __restrict__ sg,
    const float* ep, float b,
    float& cm, float& ocp0, float& ocp1, float& ocp2,
    float& am, float& oal0, float& oal1, float& oal2)
{
    float l0 = fmaf(fmaf(sg[0], ep[0], mu[0]), c0,
               fmaf(fmaf(sg[1], ep[1], mu[1]), c1,
                    fmaf(sg[2], ep[2], mu[2]) * c2));
    float l1 = fmaf(fmaf(sg[3], ep[3], mu[3]), c0,
               fmaf(fmaf(sg[4], ep[4], mu[4]), c1,
                    fmaf(sg[5], ep[5], mu[5]) * c2));
    float l2 = fmaf(fmaf(sg[6], ep[6], mu[6]), c0,
               fmaf(fmaf(sg[7], ep[7], mu[7]), c1,
                    fmaf(sg[8], ep[8], mu[8]) * c2));

    float m  = fmaxf(l0, fmaxf(l1, l2));
    float e0 = __expf(l0 - m);
    float e1 = __expf(l1 - m);
    float e2 = __expf(l2 - m);
    float inv_es = __frcp_rn(e0 + e1 + e2);
    float cp0 = e0 * inv_es;
    float cp1 = e1 * inv_es;
    float cp2 = e2 * inv_es;

    float child_sum = c0 + c1 + c2;
    float prnt_sum  = p0 + p1 + p2;
    bool child_mask = (child_sum != 0.0f);
    bool copy_mask  = child_mask && (prnt_sum == 0.0f);
    bool alpha_mask = child_mask && (prnt_sum != 0.0f);

    float z0 = fmaxf(0.01f, p0 + cp0);
    float z1 = fmaxf(0.01f, p1 + cp1);
    float z2 = fmaxf(0.01f, p2 + cp2);
    float inv_zs = __frcp_rn(z0 + z1 + z2);
    z0 *= inv_zs; z1 *= inv_zs; z2 *= inv_zs;
    float entropy = -(z0 * __logf(z0) + z1 * __logf(z1) + z2 * __logf(z2));

    float dot  = p0 * cp0 + p1 * cp1 + p2 * cp2;
    float sqp  = p0 * p0 + p1 * p1 + p2 * p2;
    float sqc  = cp0 * cp0 + cp1 * cp1 + cp2 * cp2;
    float np   = (sqp == 0.0f) ? 0.0f : __fsqrt_rn(sqp);
    float nc   = (sqc == 0.0f) ? 0.0f : __fsqrt_rn(sqc);
    float norm = np * nc;
    norm = (norm == 0.0f) ? 1.0f : norm;
    float cosv = fmaxf(0.01f, dot * __frcp_rn(norm));
    float s = 42.0f * cosv * __frcp_rn(entropy);

    float ob = 1.0f - b;
    float a0 = fmaf(ob, p0, b * cp0) * s;
    float a1 = fmaf(ob, p1, b * cp1) * s;
    float a2 = fmaf(ob, p2, b * cp2) * s;

    cm   = copy_mask ? 1.0f : 0.0f;
    ocp0 = copy_mask ? cp0 : 0.0f;
    ocp1 = copy_mask ? cp1 : 0.0f;
    ocp2 = copy_mask ? cp2 : 0.0f;
    am   = alpha_mask ? 1.0f : 0.0f;
    oal0 = alpha_mask ? a0 : 0.0f;
    oal1 = alpha_mask ? a1 : 0.0f;
    oal2 = alpha_mask ? a2 : 0.0f;
}

// ---------------------------------------------------------------------------
// SMEM-staged kernel: dense float4 global traffic, scalar per-edge compute.
// Requires n % 4 == 0 (so all section bases are 16B-aligned).
// ---------------------------------------------------------------------------
__global__ __launch_bounds__(EPB)
void alpha_model_smem(const float*  __restrict__ prnt,
                      const float*  __restrict__ child,
                      const float*  __restrict__ rel_mu,
                      const float*  __restrict__ rel_sigma,
                      const float*  __restrict__ eps,
                      const float*  __restrict__ beta,
                      const int*    __restrict__ rels,
                      float* __restrict__ out,
                      int n)
{
    __shared__ float s_mu[NRELS * 9];
    __shared__ float s_sig[NRELS * 9];
    __shared__ float s_p[EPB * 3];
    __shared__ float s_c[EPB * 3];
    __shared__ float s_e[EPB * 9];
    __shared__ float s_ocp[EPB * 3];
    __shared__ float s_oal[EPB * 3];

    int tid = threadIdx.x;
    int base = blockIdx.x * EPB;

    for (int t = tid; t < NRELS * 9; t += EPB) {
        s_mu[t]  = rel_mu[t];
        s_sig[t] = rel_sigma[t];
    }

    size_t N = n;

    if (base + EPB <= n) {
        // ---- cooperative dense float4 loads into smem ----
        const float4* gp = (const float4*)(prnt  + 3 * (size_t)base);
        const float4* gc = (const float4*)(child + 3 * (size_t)base);
        const float4* ge = (const float4*)(eps   + 9 * (size_t)base);
        if (tid < (EPB * 3) / 4) {
            ((float4*)s_p)[tid] = gp[tid];
            ((float4*)s_c)[tid] = gc[tid];
        }
        #pragma unroll
        for (int k = 0; k < (EPB * 9) / 4; k += EPB)
            ((float4*)s_e)[k + tid] = ge[k + tid];

        float b = beta[base + tid];           // dense scalar, already coalesced
        int   r = rels[base + tid];

        __syncthreads();

        // ---- per-edge compute (smem reads: stride 3 & 9, conflict-free) ----
        float p0 = s_p[3 * tid + 0], p1 = s_p[3 * tid + 1], p2 = s_p[3 * tid + 2];
        float c0 = s_c[3 * tid + 0], c1 = s_c[3 * tid + 1], c2 = s_c[3 * tid + 2];
        float ep[9];
        #pragma unroll
        for (int k = 0; k < 9; k++) ep[k] = s_e[9 * tid + k];

        float cm, ocp0, ocp1, ocp2, am, oal0, oal1, oal2;
        edge_compute(p0, p1, p2, c0, c1, c2,
                     &s_mu[9 * r], &s_sig[9 * r], ep, b,
                     cm, ocp0, ocp1, ocp2, am, oal0, oal1, oal2);

        // masks: dense scalar stores straight to global
        out[base + tid]         = cm;
        out[4 * N + base + tid] = am;

        // stage the stride-3 vectors
        s_ocp[3 * tid + 0] = ocp0; s_ocp[3 * tid + 1] = ocp1; s_ocp[3 * tid + 2] = ocp2;
        s_oal[3 * tid + 0] = oal0; s_oal[3 * tid + 1] = oal1; s_oal[3 * tid + 2] = oal2;

        __syncthreads();

        // ---- cooperative dense float4 stores ----
        float4* gocp = (float4*)(out + N     + 3 * (size_t)base);
        float4* goal = (float4*)(out + 5 * N + 3 * (size_t)base);
        if (tid < (EPB * 3) / 4) {
            gocp[tid] = ((float4*)s_ocp)[tid];
            goal[tid] = ((float4*)s_oal)[tid];
        }
    } else {
        // ---- tail: guarded scalar path (no staging) ----
        __syncthreads();
        int i = base + tid;
        if (i < n) {
            int r = rels[i];
            float b = beta[i];
            float p0 = prnt[3 * i + 0], p1 = prnt[3 * i + 1], p2 = prnt[3 * i + 2];
            float c0 = child[3 * i + 0], c1 = child[3 * i + 1], c2 = child[3 * i + 2];
            float ep[9];
            #pragma unroll
            for (int k = 0; k < 9; k++) ep[k] = eps[9 * (size_t)i + k];

            float cm, ocp0, ocp1, ocp2, am, oal0, oal1, oal2;
            edge_compute(p0, p1, p2, c0, c1, c2,
                         &s_mu[9 * r], &s_sig[9 * r], ep, b,
                         cm, ocp0, ocp1, ocp2, am, oal0, oal1, oal2);

            out[i] = cm;
            out[N + 3 * (size_t)i + 0] = ocp0;
            out[N + 3 * (size_t)i + 1] = ocp1;
            out[N + 3 * (size_t)i + 2] = ocp2;
            out[4 * N + i] = am;
            out[5 * N + 3 * (size_t)i + 0] = oal0;
            out[5 * N + 3 * (size_t)i + 1] = oal1;
            out[5 * N + 3 * (size_t)i + 2] = oal2;
        }
    }
}

// ---------------------------------------------------------------------------
// Fully scalar fallback for n % 4 != 0 (misaligned sections).
// ---------------------------------------------------------------------------
__global__ __launch_bounds__(256)
void alpha_model_scalar(const float* __restrict__ prnt,
                        const float* __restrict__ child,
                        const float* __restrict__ rel_mu,
                        const float* __restrict__ rel_sigma,
                        const float* __restrict__ eps,
                        const float* __restrict__ beta,
                        const int*   __restrict__ rels,
                        float* __restrict__ out,
                        int n)
{
    __shared__ float s_mu[NRELS * 9];
    __shared__ float s_sig[NRELS * 9];
    for (int t = threadIdx.x; t < NRELS * 9; t += blockDim.x) {
        s_mu[t]  = rel_mu[t];
        s_sig[t] = rel_sigma[t];
    }
    __syncthreads();

    int i = blockIdx.x * blockDim.x + threadIdx.x;
    if (i >= n) return;

    int r = rels[i];
    float b = beta[i];
    float p0 = prnt[3 * i + 0], p1 = prnt[3 * i + 1], p2 = prnt[3 * i + 2];
    float c0 = child[3 * i + 0], c1 = child[3 * i + 1], c2 = child[3 * i + 2];
    float ep[9];
    #pragma unroll
    for (int k = 0; k < 9; k++) ep[k] = eps[9 * (size_t)i + k];

    float cm, ocp0, ocp1, ocp2, am, oal0, oal1, oal2;
    edge_compute(p0, p1, p2, c0, c1, c2, &s_mu[9 * r], &s_sig[9 * r], ep, b,
                 cm, ocp0, ocp1, ocp2, am, oal0, oal1, oal2);

    size_t N = n;
    out[i] = cm;
    out[N + 3 * (size_t)i + 0] = ocp0;
    out[N + 3 * (size_t)i + 1] = ocp1;
    out[N + 3 * (size_t)i + 2] = ocp2;
    out[4 * N + i] = am;
    out[5 * N + 3 * (size_t)i + 0] = oal0;
    out[5 * N + 3 * (size_t)i + 1] = oal1;
    out[5 * N + 3 * (size_t)i + 2] = oal2;
}

extern "C" void kernel_launch(void* const* d_in, const int* in_sizes, int n_in,
                              void* d_out, int out_size) {
    const float* prnt   = (const float*)d_in[0];
    const float* child  = (const float*)d_in[1];
    const float* rel_mu = (const float*)d_in[2];
    const float* rel_sg = (const float*)d_in[3];
    const float* eps    = (const float*)d_in[4];
    const float* beta   = (const float*)d_in[5];
    const int*   rels   = (const int*)d_in[6];
    float* out = (float*)d_out;

    int n = in_sizes[5];  // beta element count == N
    if ((n & 3) == 0) {
        int blocks = (n + EPB - 1) / EPB;
        alpha_model_smem<<<blocks, EPB>>>(prnt, child, rel_mu, rel_sg,
                                          eps, beta, rels, out, n);
    } else {
        int threads = 256;
        int blocks = (n + threads - 1) / threads;
        alpha_model_scalar<<<blocks, threads>>>(prnt, child, rel_mu, rel_sg,
                                                eps, beta, rels, out, n);
    }
}

// round 6
// speedup vs baseline: 1.0847x; 1.0029x over previous
#include <cuda_runtime.h>
#include <cuda_bf16.h>

#define NRELS 20

__device__ __forceinline__ float ldcs_f(const float* p)  { return __ldcs(p); }
__device__ __forceinline__ int   ldcs_i(const int* p)    { return __ldcs(p); }
__device__ __forceinline__ void  stcs_f(float* p, float v) { __stcs(p, v); }

__global__ __launch_bounds__(256)
void alpha_model_stream(const float* __restrict__ prnt,
                        const float* __restrict__ child,
                        const float* __restrict__ rel_mu,
                        const float* __restrict__ rel_sigma,
                        const float* __restrict__ eps,
                        const float* __restrict__ beta,
                        const int*   __restrict__ rels,
                        float* __restrict__ out,
                        int n)
{
    __shared__ float s_mu[NRELS * 9];
    __shared__ float s_sig[NRELS * 9];
    for (int t = threadIdx.x; t < NRELS * 9; t += blockDim.x) {
        s_mu[t]  = rel_mu[t];    // tiny tables: default policy (reused by all CTAs)
        s_sig[t] = rel_sigma[t];
    }
    __syncthreads();

    int i = blockIdx.x * blockDim.x + threadIdx.x;
    if (i >= n) return;

    // ---- streaming loads (evict-first; one-touch data) ----
    int   r = ldcs_i(&rels[i]);
    float b = ldcs_f(&beta[i]);

    float p0 = ldcs_f(&prnt[3 * i + 0]);
    float p1 = ldcs_f(&prnt[3 * i + 1]);
    float p2 = ldcs_f(&prnt[3 * i + 2]);
    float c0 = ldcs_f(&child[3 * i + 0]);
    float c1 = ldcs_f(&child[3 * i + 1]);
    float c2 = ldcs_f(&child[3 * i + 2]);

    float ep[9];
    const float* epp = eps + 9 * (size_t)i;
    #pragma unroll
    for (int k = 0; k < 9; k++) ep[k] = ldcs_f(&epp[k]);

    const float* mu = &s_mu[9 * r];
    const float* sg = &s_sig[9 * r];

    // ---- M = mu + sigma*eps ; logits = M @ child ----
    float l0 = fmaf(fmaf(sg[0], ep[0], mu[0]), c0,
               fmaf(fmaf(sg[1], ep[1], mu[1]), c1,
                    fmaf(sg[2], ep[2], mu[2]) * c2));
    float l1 = fmaf(fmaf(sg[3], ep[3], mu[3]), c0,
               fmaf(fmaf(sg[4], ep[4], mu[4]), c1,
                    fmaf(sg[5], ep[5], mu[5]) * c2));
    float l2 = fmaf(fmaf(sg[6], ep[6], mu[6]), c0,
               fmaf(fmaf(sg[7], ep[7], mu[7]), c1,
                    fmaf(sg[8], ep[8], mu[8]) * c2));

    // ---- softmax ----
    float m  = fmaxf(l0, fmaxf(l1, l2));
    float e0 = __expf(l0 - m);
    float e1 = __expf(l1 - m);
    float e2 = __expf(l2 - m);
    float inv_es = __frcp_rn(e0 + e1 + e2);
    float cp0 = e0 * inv_es;
    float cp1 = e1 * inv_es;
    float cp2 = e2 * inv_es;

    // ---- masks (exact-zero semantics) ----
    float child_sum = c0 + c1 + c2;
    float prnt_sum  = p0 + p1 + p2;
    bool child_mask = (child_sum != 0.0f);
    bool copy_mask  = child_mask && (prnt_sum == 0.0f);
    bool alpha_mask = child_mask && (prnt_sum != 0.0f);

    // ---- scale ----
    float z0 = fmaxf(0.01f, p0 + cp0);
    float z1 = fmaxf(0.01f, p1 + cp1);
    float z2 = fmaxf(0.01f, p2 + cp2);
    float inv_zs = __frcp_rn(z0 + z1 + z2);
    z0 *= inv_zs; z1 *= inv_zs; z2 *= inv_zs;
    float entropy = -(z0 * __logf(z0) + z1 * __logf(z1) + z2 * __logf(z2));

    float dot  = p0 * cp0 + p1 * cp1 + p2 * cp2;
    float sqp  = p0 * p0 + p1 * p1 + p2 * p2;
    float sqc  = cp0 * cp0 + cp1 * cp1 + cp2 * cp2;
    float np   = (sqp == 0.0f) ? 0.0f : __fsqrt_rn(sqp);
    float nc   = (sqc == 0.0f) ? 0.0f : __fsqrt_rn(sqc);
    float norm = np * nc;
    norm = (norm == 0.0f) ? 1.0f : norm;
    float cosv = fmaxf(0.01f, dot * __frcp_rn(norm));
    float s = 42.0f * cosv * __frcp_rn(entropy);

    // ---- alpha ----
    float ob = 1.0f - b;
    float a0 = fmaf(ob, p0, b * cp0) * s;
    float a1 = fmaf(ob, p1, b * cp1) * s;
    float a2 = fmaf(ob, p2, b * cp2) * s;

    // ---- streaming stores ----
    size_t N = n;
    stcs_f(&out[i], copy_mask ? 1.0f : 0.0f);

    float* ocp = out + N + 3 * (size_t)i;
    stcs_f(&ocp[0], copy_mask ? cp0 : 0.0f);
    stcs_f(&ocp[1], copy_mask ? cp1 : 0.0f);
    stcs_f(&ocp[2], copy_mask ? cp2 : 0.0f);

    stcs_f(&out[4 * N + i], alpha_mask ? 1.0f : 0.0f);

    float* oal = out + 5 * N + 3 * (size_t)i;
    stcs_f(&oal[0], alpha_mask ? a0 : 0.0f);
    stcs_f(&oal[1], alpha_mask ? a1 : 0.0f);
    stcs_f(&oal[2], alpha_mask ? a2 : 0.0f);
}

extern "C" void kernel_launch(void* const* d_in, const int* in_sizes, int n_in,
                              void* d_out, int out_size) {
    const float* prnt   = (const float*)d_in[0];
    const float* child  = (const float*)d_in[1];
    const float* rel_mu = (const float*)d_in[2];
    const float* rel_sg = (const float*)d_in[3];
    const float* eps    = (const float*)d_in[4];
    const float* beta   = (const float*)d_in[5];
    const int*   rels   = (const int*)d_in[6];
    float* out = (float*)d_out;

    int n = in_sizes[5];  // beta element count == N
    int threads = 256;
    int blocks = (n + threads - 1) / threads;
    alpha_model_stream<<<blocks, threads>>>(prnt, child, rel_mu, rel_sg,
                                            eps, beta, rels, out, n);
}